// round 3
// baseline (speedup 1.0000x reference)
#include <cuda_runtime.h>
#include <math.h>
#include <stdint.h>
#include <stddef.h>

#define BB   32
#define NN   196
#define TT   128
#define DIMG 768
#define DH   512
#define VV   10000

#define NCTA 148
#define NTHR 256

// ---------------- scratch (device globals; no allocation allowed) ----------
__device__ float g_keys[BB * NN * DH];       // 12.8 MB
__device__ float g_Wk[BB * NN * DH];         // 12.8 MB
__device__ float g_Xemb[BB * TT * DH];       // 8.4 MB  emb[tgt]
__device__ float g_X[BB * TT * 4 * DH];      // 33.5 MB  x_t @ W_ih[:, :512]^T
__device__ float g_H[BB * TT * DH];          // 8.4 MB  all h_new
__device__ float g_h[BB * DH];
__device__ float g_c[BB * DH];
__device__ float g_hwh_p[8 * BB * DH];       // hWh partials (8 k-slots)
__device__ float g_sc[BB * 256];             // scores (196 used, pitch 256)
__device__ float g_ctx[BB * DH];
__device__ float g_pg[4 * BB * 4 * DH];      // gate partials (4 k-slots of 256)

__device__ volatile unsigned g_bar_epoch;
__device__ unsigned g_bar_cnt;

// ---------------- helpers ----------------------------------------------------
__device__ __forceinline__ float tanh_fast(float x) {
    float y;
    asm("tanh.approx.f32 %0, %1;" : "=f"(y) : "f"(x));
    return y;
}
__device__ __forceinline__ float sigmoidf_acc(float x) {
    return 1.0f / (1.0f + expf(-x));
}
__device__ __forceinline__ float warp_sum(float v) {
#pragma unroll
    for (int o = 16; o > 0; o >>= 1) v += __shfl_xor_sync(0xffffffffu, v, o);
    return v;
}
__device__ __forceinline__ float warp_max(float v) {
#pragma unroll
    for (int o = 16; o > 0; o >>= 1) v = fmaxf(v, __shfl_xor_sync(0xffffffffu, v, o));
    return v;
}
// 256-thread block reductions; red must hold 8 floats; leaves value in all threads.
__device__ __forceinline__ float block_sum256(float v, float* red) {
    int w = threadIdx.x >> 5, l = threadIdx.x & 31;
    v = warp_sum(v);
    if (l == 0) red[w] = v;
    __syncthreads();
    float r = red[0] + red[1] + red[2] + red[3] + red[4] + red[5] + red[6] + red[7];
    __syncthreads();
    return r;
}
__device__ __forceinline__ float block_max256(float v, float* red) {
    int w = threadIdx.x >> 5, l = threadIdx.x & 31;
    v = warp_max(v);
    if (l == 0) red[w] = v;
    __syncthreads();
    float r = red[0];
#pragma unroll
    for (int i = 1; i < 8; i++) r = fmaxf(r, red[i]);
    __syncthreads();
    return r;
}

// grid-wide barrier (all NCTA CTAs resident)
__device__ __forceinline__ void grid_barrier() {
    __threadfence();               // release all this thread's writes (gpu scope)
    __syncthreads();               // all threads of CTA fenced before arrival
    if (threadIdx.x == 0) {
        unsigned e = g_bar_epoch;
        if (atomicAdd(&g_bar_cnt, 1u) == NCTA - 1) {
            g_bar_cnt = 0;
            __threadfence();
            g_bar_epoch = e + 1;
        } else {
            while (g_bar_epoch == e) { __nanosleep(64); }
        }
    }
    __syncthreads();
    __threadfence();               // acquire: gpu-scope fence invalidates stale L1
}

// ---------------- generic tiled fp32 GEMM: C = A(MxK,lda) * B(NxK,ldb)^T ----
__global__ __launch_bounds__(256) void sgemm_nt(
    const float* __restrict__ A, int lda,
    const float* __restrict__ Bm, int ldb,
    const float* __restrict__ bias, float* __restrict__ C, int ldc,
    int M, int Nc, int K)
{
    __shared__ float As[8][128];
    __shared__ float Bs[8][128];
    int bm = blockIdx.y * 128, bn = blockIdx.x * 128;
    int tid = threadIdx.x;
    int tx = (tid & 15) * 8;
    int ty = (tid >> 4) * 8;

    float acc[8][8];
#pragma unroll
    for (int i = 0; i < 8; i++)
#pragma unroll
        for (int j = 0; j < 8; j++) acc[i][j] = 0.0f;

    for (int k0 = 0; k0 < K; k0 += 8) {
#pragma unroll
        for (int i = tid; i < 1024; i += 256) {
            int m = i >> 3, k = i & 7;
            int gm = bm + m;
            As[k][m] = (gm < M) ? A[(size_t)gm * lda + k0 + k] : 0.0f;
        }
#pragma unroll
        for (int i = tid; i < 1024; i += 256) {
            int n = i >> 3, k = i & 7;
            int gn = bn + n;
            Bs[k][n] = (gn < Nc) ? Bm[(size_t)gn * ldb + k0 + k] : 0.0f;
        }
        __syncthreads();
#pragma unroll
        for (int k = 0; k < 8; k++) {
            float4 a0 = *reinterpret_cast<const float4*>(&As[k][ty]);
            float4 a1 = *reinterpret_cast<const float4*>(&As[k][ty + 4]);
            float4 b0 = *reinterpret_cast<const float4*>(&Bs[k][tx]);
            float4 b1 = *reinterpret_cast<const float4*>(&Bs[k][tx + 4]);
            float av[8] = {a0.x, a0.y, a0.z, a0.w, a1.x, a1.y, a1.z, a1.w};
            float bv[8] = {b0.x, b0.y, b0.z, b0.w, b1.x, b1.y, b1.z, b1.w};
#pragma unroll
            for (int i = 0; i < 8; i++)
#pragma unroll
                for (int j = 0; j < 8; j++)
                    acc[i][j] = fmaf(av[i], bv[j], acc[i][j]);
        }
        __syncthreads();
    }
#pragma unroll
    for (int i = 0; i < 8; i++) {
        int gm = bm + ty + i;
        if (gm >= M) continue;
#pragma unroll
        for (int j = 0; j < 8; j++) {
            int gn = bn + tx + j;
            if (gn < Nc)
                C[(size_t)gm * ldc + gn] = acc[i][j] + (bias ? bias[gn] : 0.0f);
        }
    }
}

// ---------------- embedding gather ------------------------------------------
__global__ __launch_bounds__(256) void gather_emb(
    const int* __restrict__ tgt, const float* __restrict__ emb)
{
    int idx = blockIdx.x * 256 + threadIdx.x;
    if (idx >= BB * TT * DH) return;
    int row = idx >> 9;          // b*T+t
    int d = idx & 511;
    g_Xemb[idx] = emb[(size_t)tgt[row] * DH + d];
}

// ---------------- skinny 32xK chunk: acc += A(32x64) * B(64x64)^T ----------
// 256 threads. sA: 64*36 floats, sB: 64*65 floats.
__device__ __forceinline__ void skinny_chunk(
    const float* __restrict__ A, int lda,
    const float* __restrict__ B, int ldb,
    float acc[8], float* sA, float* sB)
{
    int tid = threadIdx.x;
    __syncthreads();   // protect smem from previous use
#pragma unroll
    for (int i = tid; i < 32 * 64; i += 256) {
        int b = i >> 6, k = i & 63;
        sA[k * 36 + b] = A[(size_t)b * lda + k];
    }
#pragma unroll
    for (int i = tid; i < 64 * 64; i += 256) {
        int n = i >> 6, k = i & 63;
        sB[k * 65 + n] = B[(size_t)n * ldb + k];
    }
    __syncthreads();
    int nl = tid & 63, bq = tid >> 6;    // 4 b-groups of 8
#pragma unroll 8
    for (int k = 0; k < 64; k++) {
        float w = sB[k * 65 + nl];
        const float4* ap = reinterpret_cast<const float4*>(&sA[k * 36 + bq * 8]);
        float4 a0 = ap[0], a1 = ap[1];
        acc[0] = fmaf(a0.x, w, acc[0]); acc[1] = fmaf(a0.y, w, acc[1]);
        acc[2] = fmaf(a0.z, w, acc[2]); acc[3] = fmaf(a0.w, w, acc[3]);
        acc[4] = fmaf(a1.x, w, acc[4]); acc[5] = fmaf(a1.y, w, acc[5]);
        acc[6] = fmaf(a1.z, w, acc[6]); acc[7] = fmaf(a1.w, w, acc[7]);
    }
}

// ---------------- persistent recurrence kernel ------------------------------
__global__ __launch_bounds__(NTHR) void recurrence(
    const float* __restrict__ cls,
    const float* __restrict__ ih_W, const float* __restrict__ ih_b,
    const float* __restrict__ ic_W, const float* __restrict__ ic_b,
    const float* __restrict__ attn_Wh, const float* __restrict__ attn_v,
    const float* __restrict__ W_ih, const float* __restrict__ W_hh,
    const float* __restrict__ b_ih, const float* __restrict__ b_hh,
    const float* __restrict__ lnw, const float* __restrict__ lnb)
{
    __shared__ float sh[64 * 36 + 64 * 65];   // 25.9 KB, aliased per phase
    float* sA = sh;
    float* sB = sh + 64 * 36;
    int tid = threadIdx.x;
    int cta = blockIdx.x;
    int nl = tid & 63, bq = tid >> 6;

    // ---- prologue: h0 = cls@ih_W^T + ih_b ; c0 = cls@ic_W^T + ic_b ----------
    for (int task = cta; task < 16; task += NCTA) {
        int mat = task >> 3;               // 0 = h0, 1 = c0
        int n0 = (task & 7) * 64;
        const float* W = mat ? ic_W : ih_W;
        const float* bias = mat ? ic_b : ih_b;
        float* dst = mat ? g_c : g_h;
        float acc[8] = {0, 0, 0, 0, 0, 0, 0, 0};
        for (int kc = 0; kc < 12; kc++)
            skinny_chunk(cls + kc * 64, DIMG, W + (size_t)n0 * DIMG + kc * 64, DIMG,
                         acc, sA, sB);
        float bv = bias[n0 + nl];
#pragma unroll
        for (int j = 0; j < 8; j++)
            dst[(size_t)(bq * 8 + j) * DH + n0 + nl] = acc[j] + bv;
    }
    grid_barrier();

    // ---- time loop ----------------------------------------------------------
    for (int t = 0; t < TT; t++) {
        // P1: hWh partials = h @ attn_Wh^T  (8 nblk x 8 kslot = 64 tasks)
        for (int task = cta; task < 64; task += NCTA) {
            int kslot = task >> 3, n0 = (task & 7) * 64, k0 = kslot * 64;
            float acc[8] = {0, 0, 0, 0, 0, 0, 0, 0};
            skinny_chunk(g_h + k0, DH, attn_Wh + (size_t)n0 * DH + k0, DH,
                         acc, sA, sB);
#pragma unroll
            for (int j = 0; j < 8; j++)
                g_hwh_p[((size_t)kslot * BB + bq * 8 + j) * DH + n0 + nl] = acc[j];
        }
        grid_barrier();

        // P2: scores  (32 b x 7 chunks of 28 n = 224 tasks)
        {
            float* hwh = sh;          // 512
            float* vsm = sh + 512;    // 512
            for (int task = cta; task < 224; task += NCTA) {
                int b = task / 7, n0 = (task % 7) * 28;
                __syncthreads();
                for (int d = tid; d < DH; d += 256) {
                    float s = 0.0f;
#pragma unroll
                    for (int s8 = 0; s8 < 8; s8++)
                        s += g_hwh_p[((size_t)s8 * BB + b) * DH + d];
                    hwh[d] = s;
                    vsm[d] = attn_v[d];
                }
                __syncthreads();
                int w = tid >> 5, l = tid & 31;
                for (int n = n0 + w; n < n0 + 28; n += 8) {
                    const float* wk = &g_Wk[((size_t)b * NN + n) * DH];
                    float e = 0.0f;
#pragma unroll 4
                    for (int k = l; k < DH; k += 32)
                        e = fmaf(tanh_fast(hwh[k] + wk[k]), vsm[k], e);
                    e = warp_sum(e);
                    if (l == 0) g_sc[b * 256 + n] = e;
                }
            }
        }
        grid_barrier();

        // P3: softmax + ctx  (32 b x 4 dchunk = 128 tasks)
        {
            float* alpha = sh;        // 256
            float* red = sh + 256;    // 8
            for (int task = cta; task < 128; task += NCTA) {
                int b = task >> 2, d0 = (task & 3) * 128;
                __syncthreads();
                float s = (tid < NN) ? g_sc[b * 256 + tid] : -1e30f;
                float m = block_max256(s, red);
                float ex = (tid < NN) ? expf(s - m) : 0.0f;
                alpha[tid] = ex;
                __syncthreads();
                float ssum = block_sum256(ex, red);
                float inv = 1.0f / ssum;
                if (tid < 128) {
                    int d = d0 + tid;
                    float ctx = 0.0f;
                    const float* kb = &g_keys[(size_t)b * NN * DH + d];
                    for (int n = 0; n < NN; n++)
                        ctx = fmaf(alpha[n], kb[(size_t)n * DH], ctx);
                    g_ctx[b * DH + d] = ctx * inv;
                }
            }
        }
        grid_barrier();

        // P4: gate partials  (32 nblk x 4 kslots of 256 = 128 tasks)
        // K-space [0,1024): k<512 -> ctx . W_ih[n, 512+k] ; else h . W_hh[n, k-512]
        for (int task = cta; task < 128; task += NCTA) {
            int kslot = task >> 5, n0 = (task & 31) * 64, k0 = kslot * 256;
            float acc[8] = {0, 0, 0, 0, 0, 0, 0, 0};
            for (int kc = 0; kc < 4; kc++) {
                int kk = k0 + kc * 64;
                if (kk < 512)
                    skinny_chunk(g_ctx + kk, DH,
                                 W_ih + (size_t)n0 * (2 * DH) + DH + kk, 2 * DH,
                                 acc, sA, sB);
                else
                    skinny_chunk(g_h + (kk - 512), DH,
                                 W_hh + (size_t)n0 * DH + (kk - 512), DH,
                                 acc, sA, sB);
            }
#pragma unroll
            for (int j = 0; j < 8; j++)
                g_pg[((size_t)kslot * BB + bq * 8 + j) * (4 * DH) + n0 + nl] = acc[j];
        }
        grid_barrier();

        // P5: cell + layernorm  (32 tasks, one per b; 2 d per thread)
        {
            float* red = sh;
            for (int task = cta; task < BB; task += NCTA) {
                int b = task;
                size_t xrow = ((size_t)b * TT + t) * (4 * DH);
                float hr[2], cn[2];
#pragma unroll
                for (int half = 0; half < 2; half++) {
                    int d = tid + half * 256;
                    float gi = 0.f, gf = 0.f, gg = 0.f, go = 0.f;
#pragma unroll
                    for (int s = 0; s < 4; s++) {
                        const float* p = g_pg + ((size_t)s * BB + b) * (4 * DH);
                        gi += p[d]; gf += p[DH + d];
                        gg += p[2 * DH + d]; go += p[3 * DH + d];
                    }
                    const float* xp = g_X + xrow;
                    gi += xp[d] + b_ih[d] + b_hh[d];
                    gf += xp[DH + d] + b_ih[DH + d] + b_hh[DH + d];
                    gg += xp[2 * DH + d] + b_ih[2 * DH + d] + b_hh[2 * DH + d];
                    go += xp[3 * DH + d] + b_ih[3 * DH + d] + b_hh[3 * DH + d];
                    float c = g_c[b * DH + d];
                    cn[half] = sigmoidf_acc(gf) * c + sigmoidf_acc(gi) * tanhf(gg);
                    hr[half] = sigmoidf_acc(go) * tanhf(cn[half]);
                }
                __syncthreads();
                float mu = block_sum256(hr[0] + hr[1], red) * (1.0f / DH);
                float va = block_sum256(hr[0] * hr[0] + hr[1] * hr[1], red) * (1.0f / DH)
                           - mu * mu;
                float rstd = rsqrtf(va + 1e-5f);
#pragma unroll
                for (int half = 0; half < 2; half++) {
                    int d = tid + half * 256;
                    float hn = (hr[half] - mu) * rstd * lnw[d] + lnb[d];
                    g_c[b * DH + d] = cn[half];
                    g_h[b * DH + d] = hn;
                    g_H[((size_t)b * TT + t) * DH + d] = hn;
                }
            }
        }
        grid_barrier();
    }
}

// ---------------- launcher ---------------------------------------------------
extern "C" void kernel_launch(void* const* d_in, const int* in_sizes, int n_in,
                              void* d_out, int out_size)
{
    (void)in_sizes; (void)n_in; (void)out_size;
    const float* patches = (const float*)d_in[0];
    const float* cls     = (const float*)d_in[1];
    const int*   tgt     = (const int*)  d_in[2];
    const float* emb     = (const float*)d_in[3];
    const float* kv_W    = (const float*)d_in[4];
    const float* kv_b    = (const float*)d_in[5];
    const float* ih_W    = (const float*)d_in[6];
    const float* ih_b    = (const float*)d_in[7];
    const float* ic_W    = (const float*)d_in[8];
    const float* ic_b    = (const float*)d_in[9];
    const float* attn_Wh = (const float*)d_in[10];
    const float* attn_Wk = (const float*)d_in[11];
    const float* attn_v  = (const float*)d_in[12];
    const float* W_ih    = (const float*)d_in[13];
    const float* W_hh    = (const float*)d_in[14];
    const float* b_ih    = (const float*)d_in[15];
    const float* b_hh    = (const float*)d_in[16];
    const float* ln_w    = (const float*)d_in[17];
    const float* ln_b    = (const float*)d_in[18];
    const float* out_W   = (const float*)d_in[19];
    const float* out_b   = (const float*)d_in[20];
    float* out = (float*)d_out;

    float *p_keys, *p_Wk, *p_Xemb, *p_X, *p_H;
    cudaGetSymbolAddress((void**)&p_keys, g_keys);
    cudaGetSymbolAddress((void**)&p_Wk,   g_Wk);
    cudaGetSymbolAddress((void**)&p_Xemb, g_Xemb);
    cudaGetSymbolAddress((void**)&p_X,    g_X);
    cudaGetSymbolAddress((void**)&p_H,    g_H);

    // ---- precompute (all parallel-friendly GEMMs) ----
    // keys = patches @ kv_W^T + kv_b : [6272, 512], K=768
    sgemm_nt<<<dim3(DH / 128, (BB * NN) / 128), 256>>>(
        patches, DIMG, kv_W, DIMG, kv_b, p_keys, DH, BB * NN, DH, DIMG);
    // Wk_keys = keys @ attn_Wk^T : [6272, 512], K=512
    sgemm_nt<<<dim3(DH / 128, (BB * NN) / 128), 256>>>(
        p_keys, DH, attn_Wk, DH, nullptr, p_Wk, DH, BB * NN, DH, DH);
    // Xemb = emb[tgt] : [4096, 512]
    gather_emb<<<(BB * TT * DH + 255) / 256, 256>>>(tgt, emb);
    // X = Xemb @ W_ih[:, :512]^T : [4096, 2048], K=512  (x-side of gates, hoisted)
    sgemm_nt<<<dim3((4 * DH) / 128, (BB * TT) / 128), 256>>>(
        p_Xemb, DH, W_ih, 2 * DH, nullptr, p_X, 4 * DH, BB * TT, 4 * DH, DH);

    // ---- persistent recurrence: h0/c0 + 128 steps in ONE kernel ----
    recurrence<<<NCTA, NTHR>>>(cls, ih_W, ih_b, ic_W, ic_b,
                               attn_Wh, attn_v, W_ih, W_hh, b_ih, b_hh,
                               ln_w, ln_b);

    // ---- deferred logits: out[b,t,:] = H @ out_W^T + out_b : [4096, 10000], K=512
    sgemm_nt<<<dim3((VV + 127) / 128, (BB * TT) / 128), 256>>>(
        p_H, DH, out_W, DH, out_b, out, VV, BB * TT, VV, DH);
}